// round 12
// baseline (speedup 1.0000x reference)
#include <cuda_runtime.h>
#include <cuda_bf16.h>

// Problem constants (fixed shapes per reference setup_inputs)
#define B_   32
#define C_   4
#define P_   (360 * 640)      // 230400
#define L_   5
#define NVEC (P_ / 4)         // 57600 vec4 groups per batch

#define NBLK 60               // blocks per batch (champion config)
#define TPB  256

#define DELTA_V 1.0f
#define DELTA_D 6.0f

// ---- static scratch (no device allocation allowed; zero-initialized at load) ----
__device__ float    g_sums[B_ * L_ * 5];         // [B][L][ch0..ch3, count] (reset by means)
__device__ float    g_means[B_ * (L_ + 1) * C_]; // [B][6][4], lane 0 = zeros
__device__ int      g_valid[B_ * (L_ + 1)];      // [B][6], lane 0 = 0
__device__ float    g_scalars[4];                // 0: dist_sum, 1: point_count, 2: var_loss
__device__ int      g_dist_done;                 // dist last-block counter (self-resetting)
__device__ unsigned g_tpack[B_ * NVEC];          // 4 uint8 labels per word

__device__ __forceinline__ float sqrt_approx(float x) {
    float r;
    asm("sqrt.approx.f32 %0, %1;" : "=f"(r) : "f"(x));
    return r;
}

// --------------------------------------------------------------------------
// Pass 1: per-(batch, lane) channel sums + (float) counts — all 25
// accumulators uniform FFMA on the FMA pipe; branch-free select; plain C.
// Unroll 1 to keep regs low / occupancy high. Plus uint8 label re-pack.
__global__ void accum_kernel(const int* __restrict__ tg,
                             const float* __restrict__ emb) {
    const int b = blockIdx.y;
    const int4*   t4 = (const int4*)(tg + (size_t)b * P_);
    const float4* e4 = (const float4*)(emb + (size_t)b * C_ * P_);
    unsigned*     tp = g_tpack + (size_t)b * NVEC;

    float s[L_][5];   // ch0..ch3, count
#pragma unroll
    for (int l = 0; l < L_; l++)
#pragma unroll
        for (int v = 0; v < 5; v++) s[l][v] = 0.0f;

#pragma unroll 1
    for (int i = blockIdx.x * blockDim.x + threadIdx.x; i < NVEC;
         i += gridDim.x * blockDim.x) {
        int4 tv = __ldcs(&t4[i]);
        float4 ev[C_];
#pragma unroll
        for (int c = 0; c < C_; c++) ev[c] = __ldcs(&e4[(size_t)c * NVEC + i]);

        tp[i] = (unsigned)tv.x | ((unsigned)tv.y << 8) |
                ((unsigned)tv.z << 16) | ((unsigned)tv.w << 24);

        int tj[4] = {tv.x, tv.y, tv.z, tv.w};
#pragma unroll
        for (int j = 0; j < 4; j++) {
            const int tt = tj[j];
#pragma unroll
            for (int l = 0; l < L_; l++) {
                const float fm = (tt == l + 1) ? 1.0f : 0.0f;
#pragma unroll
                for (int c = 0; c < C_; c++)
                    s[l][c] = fmaf(fm, ((const float*)&ev[c])[j], s[l][c]);
                s[l][4] = fmaf(fm, 1.0f, s[l][4]);   // count on FMA pipe
            }
        }
    }

    // warp reduce (25 uniform floats)
#pragma unroll
    for (int l = 0; l < L_; l++) {
#pragma unroll
        for (int off = 16; off > 0; off >>= 1) {
#pragma unroll
            for (int v = 0; v < 5; v++)
                s[l][v] += __shfl_down_sync(0xffffffffu, s[l][v], off);
        }
    }

    __shared__ float ss[L_ * 5];
    if (threadIdx.x < L_ * 5) ss[threadIdx.x] = 0.0f;
    __syncthreads();

    if ((threadIdx.x & 31) == 0) {
#pragma unroll
        for (int l = 0; l < L_; l++)
#pragma unroll
            for (int v = 0; v < 5; v++) atomicAdd(&ss[l * 5 + v], s[l][v]);
    }
    __syncthreads();

    if (threadIdx.x < L_ * 5)
        atomicAdd(&g_sums[b * L_ * 5 + threadIdx.x], ss[threadIdx.x]);
}

// --------------------------------------------------------------------------
// Means, validity, point_count, push loss; also RESETS g_sums and
// g_scalars[0] for the next graph replay. 1 warp, thread b handles batch b.
__global__ void means_kernel() {
    const int b = threadIdx.x;  // 0..31

    float mean[L_][C_];
    int   vld[L_];
    float pc_local = 0.0f;

#pragma unroll
    for (int l = 0; l < L_; l++) {
        const float cc = g_sums[b * L_ * 5 + l * 5 + 4];   // exact small integer
        vld[l] = (cc > 1.5f);
        const float inv = 1.0f / fmaxf(cc, 1.0f);
#pragma unroll
        for (int ch = 0; ch < C_; ch++) {
            const float m = g_sums[b * L_ * 5 + l * 5 + ch] * inv;
            mean[l][ch] = m;
            g_means[(b * (L_ + 1) + (l + 1)) * C_ + ch] = m;
            g_sums[b * L_ * 5 + l * 5 + ch] = 0.0f;        // reset for replay
        }
        g_sums[b * L_ * 5 + l * 5 + 4] = 0.0f;             // reset for replay
        g_valid[b * (L_ + 1) + (l + 1)] = vld[l];
        if (vld[l]) pc_local += cc;
    }
#pragma unroll
    for (int ch = 0; ch < C_; ch++) g_means[b * (L_ + 1) * C_ + ch] = 0.0f;
    g_valid[b * (L_ + 1)] = 0;

    // push loss over lane pairs (i < j, both valid)
    float psum = 0.0f;
    int npairs = 0;
#pragma unroll
    for (int i = 0; i < L_; i++) {
#pragma unroll
        for (int j = i + 1; j < L_; j++) {
            if (vld[i] && vld[j]) {
                float sq = 0.0f;
#pragma unroll
                for (int ch = 0; ch < C_; ch++) {
                    const float d = mean[i][ch] - mean[j][ch];
                    sq = fmaf(d, d, sq);
                }
                const float pd = sqrtf(fmaxf(sq, 1e-12f));
                const float ph = fmaxf(DELTA_D - pd, 0.0f);
                psum += ph * ph;
                npairs++;
            }
        }
    }
    const float var_b = (npairs > 0) ? psum / (float)npairs : 0.0f;
    const float has   = (npairs > 0) ? 1.0f : 0.0f;

    float var_sum = var_b, nb = has, pc = pc_local;
#pragma unroll
    for (int off = 16; off > 0; off >>= 1) {
        var_sum += __shfl_down_sync(0xffffffffu, var_sum, off);
        nb      += __shfl_down_sync(0xffffffffu, nb, off);
        pc      += __shfl_down_sync(0xffffffffu, pc, off);
    }
    if (threadIdx.x == 0) {
        g_scalars[0] = 0.0f;   // dist accumulator (reset before dist runs)
        g_scalars[1] = pc;
        g_scalars[2] = (nb > 0.0f) ? var_sum / fmaxf(nb, 1.0f) : 0.0f;
        __threadfence();
    }
}

// --------------------------------------------------------------------------
// Pass 2: per-point pull hinge^2 from packed uint8 labels (4 B/group).
// Means cached in shared; one global atomic per block; last-finishing block
// writes the final scalar.  [R11 verbatim]
__global__ void dist_kernel(const float* __restrict__ emb,
                            float* __restrict__ out) {
    const int b = blockIdx.y;
    __shared__ float sm[(L_ + 1) * C_];
    __shared__ int   sv[L_ + 1];
    if (threadIdx.x < (L_ + 1) * C_) sm[threadIdx.x] = g_means[b * (L_ + 1) * C_ + threadIdx.x];
    if (threadIdx.x < (L_ + 1))      sv[threadIdx.x] = g_valid[b * (L_ + 1) + threadIdx.x];
    __syncthreads();

    const unsigned* tp = g_tpack + (size_t)b * NVEC;
    const float4*   e4 = (const float4*)(emb + (size_t)b * C_ * P_);

    float local = 0.0f;
    for (int i = blockIdx.x * blockDim.x + threadIdx.x; i < NVEC;
         i += gridDim.x * blockDim.x) {
        const unsigned u = __ldcs(&tp[i]);
        float4 ev[C_];
#pragma unroll
        for (int c = 0; c < C_; c++) ev[c] = __ldcs(&e4[(size_t)c * NVEC + i]);

        int tj[4] = {(int)(u & 255u), (int)((u >> 8) & 255u),
                     (int)((u >> 16) & 255u), (int)(u >> 24)};
#pragma unroll
        for (int j = 0; j < 4; j++) {
            const int tt = tj[j];
            if (sv[tt]) {
                float sq = 0.0f;
#pragma unroll
                for (int c = 0; c < C_; c++) {
                    const float d = ((const float*)&ev[c])[j] - sm[tt * C_ + c];
                    sq = fmaf(d, d, sq);
                }
                const float dist = sqrt_approx(fmaxf(sq, 1e-12f));
                const float h = dist - DELTA_V;
                if (h > 0.0f) local = fmaf(h, h, local);
            }
        }
    }

    // warp reduce
#pragma unroll
    for (int off = 16; off > 0; off >>= 1)
        local += __shfl_down_sync(0xffffffffu, local, off);

    __shared__ float sred;
    if (threadIdx.x == 0) sred = 0.0f;
    __syncthreads();
    if ((threadIdx.x & 31) == 0) atomicAdd(&sred, local);
    __syncthreads();

    if (threadIdx.x == 0) {
        atomicAdd(&g_scalars[0], sred);
        __threadfence();
        const int old = atomicAdd(&g_dist_done, 1);
        if (old == NBLK * B_ - 1) {
            const float ds = g_scalars[0];
            const float pc = g_scalars[1];
            const float dl = (pc > 0.0f) ? ds / fmaxf(pc, 1.0f) : 0.0f;
            out[0] = dl + g_scalars[2];
            g_dist_done = 0;       // reset for next graph replay
            __threadfence();
        }
    }
}

// --------------------------------------------------------------------------
extern "C" void kernel_launch(void* const* d_in, const int* in_sizes, int n_in,
                              void* d_out, int out_size) {
    const int*   tg  = (const int*)d_in[0];    // targets [32,360,640] int32
    const float* emb = (const float*)d_in[1];  // embedding [32,4,360,640] f32
    float* out = (float*)d_out;

    dim3 grid(NBLK, B_);
    accum_kernel<<<grid, TPB>>>(tg, emb);
    means_kernel<<<1, 32>>>();
    dist_kernel<<<grid, TPB>>>(emb, out);
}